// round 15
// baseline (speedup 1.0000x reference)
#include <cuda_runtime.h>
#include <math.h>

#define DIM 4096
#define ROW4 (DIM / 4)          // 1024 float4 per row
#define BATCH 8192
#define NUM_LAYERS 6
#define NTHREADS 256            // 8 warps; CTA handles 2 rows
#define NWARPS (NTHREADS / 32)
#define VPT 4                   // float4 per thread per row: 256*4 = 1024

#define STATS_THREADS 256

// g_stats layout: [0..2] inv_norm(E,C,N); [3..5] G00,G11,G22; [6..8] G01,G02,G12
__device__ float g_stats[9];

__device__ __forceinline__ float dot4(float4 a, float4 b) {
    return a.x * b.x + a.y * b.y + a.z * b.z + a.w * b.w;
}

// ---------------------------------------------------------------------------
// Kernel 0: anchor norms + normalized Gram matrix (one block, vectorized)
// ---------------------------------------------------------------------------
__global__ void anchor_stats_kernel(const float* __restrict__ aE,
                                    const float* __restrict__ aC,
                                    const float* __restrict__ aN) {
    __shared__ float red[6][STATS_THREADS / 32];
    float s[6] = {0.f, 0.f, 0.f, 0.f, 0.f, 0.f};
    const float4* e4 = (const float4*)aE;
    const float4* c4 = (const float4*)aC;
    const float4* n4 = (const float4*)aN;
#pragma unroll
    for (int i = 0; i < DIM / 4 / STATS_THREADS; i++) {
        int idx = threadIdx.x + i * STATS_THREADS;
        float4 e = __ldg(e4 + idx);
        float4 c = __ldg(c4 + idx);
        float4 n = __ldg(n4 + idx);
        s[0] += dot4(e, e); s[1] += dot4(c, c); s[2] += dot4(n, n);
        s[3] += dot4(e, c); s[4] += dot4(e, n); s[5] += dot4(c, n);
    }
#pragma unroll
    for (int off = 16; off; off >>= 1) {
#pragma unroll
        for (int j = 0; j < 6; j++) s[j] += __shfl_xor_sync(0xffffffffu, s[j], off);
    }
    int warp = threadIdx.x >> 5, lane = threadIdx.x & 31;
    if (lane == 0) {
#pragma unroll
        for (int j = 0; j < 6; j++) red[j][warp] = s[j];
    }
    __syncthreads();
    if (threadIdx.x == 0) {
        float d[6];
#pragma unroll
        for (int j = 0; j < 6; j++) {
            float v = 0.f;
#pragma unroll
            for (int w = 0; w < STATS_THREADS / 32; w++) v += red[j][w];
            d[j] = v;
        }
        float i0 = 1.0f / fmaxf(sqrtf(d[0]), 1e-12f);
        float i1 = 1.0f / fmaxf(sqrtf(d[1]), 1e-12f);
        float i2 = 1.0f / fmaxf(sqrtf(d[2]), 1e-12f);
        g_stats[0] = i0; g_stats[1] = i1; g_stats[2] = i2;
        g_stats[3] = d[0] * i0 * i0;   // G00
        g_stats[4] = d[1] * i1 * i1;   // G11
        g_stats[5] = d[2] * i2 * i2;   // G22
        g_stats[6] = d[3] * i0 * i1;   // G01
        g_stats[7] = d[4] * i0 * i2;   // G02
        g_stats[8] = d[5] * i1 * i2;   // G12
    }
}

// ---------------------------------------------------------------------------
// Kernel 1: CTA (256 thr) = 2 rows. h rows are staged in SHARED MEMORY
// (32 KB/CTA) instead of registers: h0 read from DRAM exactly once, regs
// stay ~48 -> 5 CTAs/SM (62% occ). One anchor load serves both rows in both
// phases. Epilogue reads h back from smem (same thread wrote it: no sync).
// ---------------------------------------------------------------------------
__global__ __launch_bounds__(NTHREADS, 5)
void collapse_kernel(const float* __restrict__ h0,
                     const float* __restrict__ aE,
                     const float* __restrict__ aC,
                     const float* __restrict__ aN,
                     float* __restrict__ out) {
    const int tid = threadIdx.x;
    const int lane = tid & 31;
    const int warp = tid >> 5;
    const int b0 = blockIdx.x * 2;           // rows b0, b0+1

    __shared__ float4 sh[2 * ROW4];           // 32 KB: both h rows
    __shared__ float red[8][NWARPS];          // 8 scalars x 8 warps

    float* outH = out;
    float* outA = out + (size_t)BATCH * DIM;
    float* outD = outA + (size_t)NUM_LAYERS * BATCH * 3;
    float* outT = outD + (size_t)NUM_LAYERS * BATCH * 3;

    const float4* hrow0 = (const float4*)(h0 + (size_t)b0 * DIM);
    const float4* hrow1 = hrow0 + ROW4;
    const float4* e4 = (const float4*)aE;
    const float4* c4 = (const float4*)aC;
    const float4* n4 = (const float4*)aN;

    // ---- dot phase: load h (once), stash to smem, shared anchor loads ----
    float hhA = 0.f, sA0 = 0.f, sA1 = 0.f, sA2 = 0.f;
    float hhB = 0.f, sB0 = 0.f, sB1 = 0.f, sB2 = 0.f;
#pragma unroll
    for (int i = 0; i < VPT; i++) {
        int idx = tid + i * NTHREADS;
        float4 ha = __ldcs(hrow0 + idx);
        float4 hb = __ldcs(hrow1 + idx);
        float4 e  = __ldg(e4 + idx);
        float4 c  = __ldg(c4 + idx);
        float4 n  = __ldg(n4 + idx);
        sh[idx]        = ha;
        sh[ROW4 + idx] = hb;
        hhA += dot4(ha, ha);  hhB += dot4(hb, hb);
        sA0 += dot4(ha, e);   sB0 += dot4(hb, e);
        sA1 += dot4(ha, c);   sB1 += dot4(hb, c);
        sA2 += dot4(ha, n);   sB2 += dot4(hb, n);
    }

    // ---- warp reduce, then one block sync ----
#pragma unroll
    for (int off = 16; off; off >>= 1) {
        hhA += __shfl_xor_sync(0xffffffffu, hhA, off);
        sA0 += __shfl_xor_sync(0xffffffffu, sA0, off);
        sA1 += __shfl_xor_sync(0xffffffffu, sA1, off);
        sA2 += __shfl_xor_sync(0xffffffffu, sA2, off);
        hhB += __shfl_xor_sync(0xffffffffu, hhB, off);
        sB0 += __shfl_xor_sync(0xffffffffu, sB0, off);
        sB1 += __shfl_xor_sync(0xffffffffu, sB1, off);
        sB2 += __shfl_xor_sync(0xffffffffu, sB2, off);
    }
    if (lane == 0) {
        red[0][warp] = hhA; red[1][warp] = sA0; red[2][warp] = sA1; red[3][warp] = sA2;
        red[4][warp] = hhB; red[5][warp] = sB0; red[6][warp] = sB1; red[7][warp] = sB2;
    }
    __syncthreads();

    float tot[8];
#pragma unroll
    for (int j = 0; j < 8; j++) {
        float v = 0.f;
#pragma unroll
        for (int w = 0; w < NWARPS; w++) v += red[j][w];
        tot[j] = v;
    }

    const float invn0 = g_stats[0], invn1 = g_stats[1], invn2 = g_stats[2];
    const float G00 = g_stats[3], G11 = g_stats[4], G22 = g_stats[5];
    const float G01 = g_stats[6], G02 = g_stats[7], G12 = g_stats[8];

    // ---- two interleaved scalar recurrences (uniform across threads) ----
    float hh[2]  = { tot[0], tot[4] };
    float a0[2]  = { tot[1] * invn0, tot[5] * invn0 };
    float a1[2]  = { tot[2] * invn1, tot[6] * invn1 };
    float a2[2]  = { tot[3] * invn2, tot[7] * invn2 };
    float ch[2]  = { 1.f, 1.f };
    float c0[2]  = { 0.f, 0.f }, c1[2] = { 0.f, 0.f }, c2[2] = { 0.f, 0.f };

#pragma unroll
    for (int l = 0; l < NUM_LAYERS; l++) {
        float al0[2], al1[2], al2[2], dv0[2], dv1[2], dv2[2];
#pragma unroll
        for (int r = 0; r < 2; r++) {
            float invh = rsqrtf(fmaxf(hh[r], 1e-24f));
            al0[r] = a0[r] * invh; al1[r] = a1[r] * invh; al2[r] = a2[r] * invh;
            dv0[r] = 1.f - al0[r]; dv1[r] = 1.f - al1[r]; dv2[r] = 1.f - al2[r];
        }
        // warp0 lanes 0,1 write the two rows' traces (values uniform)
        if (warp == 0 && lane < 2) {
            size_t o = ((size_t)l * BATCH + b0 + lane) * 3;
            outA[o] = al0[lane]; outA[o + 1] = al1[lane]; outA[o + 2] = al2[lane];
            outD[o] = dv0[lane]; outD[o + 1] = dv1[lane]; outD[o + 2] = dv2[lane];
            outT[o] = fmaxf(dv0[lane], 0.f);
            outT[o + 1] = fmaxf(dv1[lane], 0.f);
            outT[o + 2] = fmaxf(dv2[lane], 0.f);
        }
#pragma unroll
        for (int r = 0; r < 2; r++) {
            float k0 = 0.10f * dv0[r] * rsqrtf(fmaxf(hh[r] - 2.f * a0[r] + G00, 1e-24f));
            float k1 = 0.10f * dv1[r] * rsqrtf(fmaxf(hh[r] - 2.f * a1[r] + G11, 1e-24f));
            float k2 = 0.05f * dv2[r] * rsqrtf(fmaxf(hh[r] - 2.f * a2[r] + G22, 1e-24f));
            float alpha = 1.f - (k0 + k1 + k2);

            float na0 = alpha * a0[r] + k0 * G00 + k1 * G01 + k2 * G02;
            float na1 = alpha * a1[r] + k0 * G01 + k1 * G11 + k2 * G12;
            float na2 = alpha * a2[r] + k0 * G02 + k1 * G12 + k2 * G22;
            float cross = k0 * k0 * G00 + k1 * k1 * G11 + k2 * k2 * G22
                        + 2.f * (k0 * k1 * G01 + k0 * k2 * G02 + k1 * k2 * G12);
            float nhh = alpha * alpha * hh[r]
                      + 2.f * alpha * (k0 * a0[r] + k1 * a1[r] + k2 * a2[r]) + cross;

            ch[r] *= alpha;
            c0[r] = alpha * c0[r] + k0;
            c1[r] = alpha * c1[r] + k1;
            c2[r] = alpha * c2[r] + k2;
            hh[r] = fmaxf(nhh, 0.f);
            a0[r] = na0; a1[r] = na1; a2[r] = na2;

            float nn = sqrtf(hh[r]);
            if (nn > 10.0f) {
                float sc = __fdividef(10.0f, nn + 1e-8f);
                ch[r] *= sc; c0[r] *= sc; c1[r] *= sc; c2[r] *= sc;
                a0[r] *= sc; a1[r] *= sc; a2[r] *= sc;
                hh[r] *= sc * sc;
            }
        }
    }

    const float chA = ch[0], bEA = c0[0] * invn0, bCA = c1[0] * invn1, bNA = c2[0] * invn2;
    const float chB = ch[1], bEB = c0[1] * invn0, bCB = c1[1] * invn1, bNB = c2[1] * invn2;

    // ---- epilogue: h from smem (same-thread data, no sync needed),
    //      shared anchor loads, streaming stores ----
    float4* orow0 = (float4*)(outH + (size_t)b0 * DIM);
    float4* orow1 = orow0 + ROW4;
#pragma unroll
    for (int i = 0; i < VPT; i++) {
        int idx = tid + i * NTHREADS;
        float4 ha = sh[idx];
        float4 hb = sh[ROW4 + idx];
        float4 e  = __ldg(e4 + idx);
        float4 c  = __ldg(c4 + idx);
        float4 n  = __ldg(n4 + idx);
        float4 oa, ob;
        oa.x = chA * ha.x + bEA * e.x + bCA * c.x + bNA * n.x;
        oa.y = chA * ha.y + bEA * e.y + bCA * c.y + bNA * n.y;
        oa.z = chA * ha.z + bEA * e.z + bCA * c.z + bNA * n.z;
        oa.w = chA * ha.w + bEA * e.w + bCA * c.w + bNA * n.w;
        ob.x = chB * hb.x + bEB * e.x + bCB * c.x + bNB * n.x;
        ob.y = chB * hb.y + bEB * e.y + bCB * c.y + bNB * n.y;
        ob.z = chB * hb.z + bEB * e.z + bCB * c.z + bNB * n.z;
        ob.w = chB * hb.w + bEB * e.w + bCB * c.w + bNB * n.w;
        __stcs(orow0 + idx, oa);
        __stcs(orow1 + idx, ob);
    }
}

extern "C" void kernel_launch(void* const* d_in, const int* in_sizes, int n_in,
                              void* d_out, int out_size) {
    const float* h0 = (const float*)d_in[0];
    const float* aE = (const float*)d_in[1];
    const float* aC = (const float*)d_in[2];
    const float* aN = (const float*)d_in[3];
    float* out = (float*)d_out;

    anchor_stats_kernel<<<1, STATS_THREADS>>>(aE, aC, aN);
    collapse_kernel<<<BATCH / 2, NTHREADS>>>(h0, aE, aC, aN, out);
}

// round 17
// speedup vs baseline: 1.4321x; 1.4321x over previous
#include <cuda_runtime.h>
#include <math.h>

#define DIM 4096
#define ROW4 (DIM / 4)          // 1024 float4 per row
#define BATCH 8192
#define NUM_LAYERS 6
#define NTHREADS 128            // 4 warps = 1 row
#define NWARPS (NTHREADS / 32)
#define VPT 8                   // float4 per thread: 128*8 = 1024 (full row)

#define STATS_THREADS 256

// g_stats layout: [0..2] inv_norm(E,C,N); [3..5] G00,G11,G22; [6..8] G01,G02,G12
__device__ float g_stats[9];

__device__ __forceinline__ float dot4(float4 a, float4 b) {
    return a.x * b.x + a.y * b.y + a.z * b.z + a.w * b.w;
}

// ---------------------------------------------------------------------------
// Kernel 0: anchor norms + normalized Gram matrix (one block, vectorized)
// ---------------------------------------------------------------------------
__global__ void anchor_stats_kernel(const float* __restrict__ aE,
                                    const float* __restrict__ aC,
                                    const float* __restrict__ aN) {
    __shared__ float red[6][STATS_THREADS / 32];
    float s[6] = {0.f, 0.f, 0.f, 0.f, 0.f, 0.f};
    const float4* e4 = (const float4*)aE;
    const float4* c4 = (const float4*)aC;
    const float4* n4 = (const float4*)aN;
#pragma unroll
    for (int i = 0; i < DIM / 4 / STATS_THREADS; i++) {
        int idx = threadIdx.x + i * STATS_THREADS;
        float4 e = __ldg(e4 + idx);
        float4 c = __ldg(c4 + idx);
        float4 n = __ldg(n4 + idx);
        s[0] += dot4(e, e); s[1] += dot4(c, c); s[2] += dot4(n, n);
        s[3] += dot4(e, c); s[4] += dot4(e, n); s[5] += dot4(c, n);
    }
#pragma unroll
    for (int off = 16; off; off >>= 1) {
#pragma unroll
        for (int j = 0; j < 6; j++) s[j] += __shfl_xor_sync(0xffffffffu, s[j], off);
    }
    int warp = threadIdx.x >> 5, lane = threadIdx.x & 31;
    if (lane == 0) {
#pragma unroll
        for (int j = 0; j < 6; j++) red[j][warp] = s[j];
    }
    __syncthreads();
    if (threadIdx.x == 0) {
        float d[6];
#pragma unroll
        for (int j = 0; j < 6; j++) {
            float v = 0.f;
#pragma unroll
            for (int w = 0; w < STATS_THREADS / 32; w++) v += red[j][w];
            d[j] = v;
        }
        float i0 = 1.0f / fmaxf(sqrtf(d[0]), 1e-12f);
        float i1 = 1.0f / fmaxf(sqrtf(d[1]), 1e-12f);
        float i2 = 1.0f / fmaxf(sqrtf(d[2]), 1e-12f);
        g_stats[0] = i0; g_stats[1] = i1; g_stats[2] = i2;
        g_stats[3] = d[0] * i0 * i0;   // G00
        g_stats[4] = d[1] * i1 * i1;   // G11
        g_stats[5] = d[2] * i2 * i2;   // G22
        g_stats[6] = d[3] * i0 * i1;   // G01
        g_stats[7] = d[4] * i0 * i2;   // G02
        g_stats[8] = d[5] * i1 * i2;   // G12
    }
}

// ---------------------------------------------------------------------------
// Kernel 1: CTA (128 thr, 4 warps) = 1 row, h held in registers (8 x float4
// per thread) across dot -> recurrence -> epilogue. h0 read from DRAM exactly
// once, no reload. 8 CTAs/SM (32 warps) hide anchor L1-hit latency.
// One 4-warp sync exchanges 4 partial sums; recurrence redundant (uniform).
// ---------------------------------------------------------------------------
__global__ __launch_bounds__(NTHREADS, 8)
void collapse_kernel(const float* __restrict__ h0,
                     const float* __restrict__ aE,
                     const float* __restrict__ aC,
                     const float* __restrict__ aN,
                     float* __restrict__ out) {
    const int tid = threadIdx.x;
    const int lane = tid & 31;
    const int warp = tid >> 5;
    const int b = blockIdx.x;

    __shared__ float red[4][NWARPS];

    float* outH = out;
    float* outA = out + (size_t)BATCH * DIM;
    float* outD = outA + (size_t)NUM_LAYERS * BATCH * 3;
    float* outT = outD + (size_t)NUM_LAYERS * BATCH * 3;

    const float4* hrow = (const float4*)(h0 + (size_t)b * DIM);
    const float4* e4 = (const float4*)aE;
    const float4* c4 = (const float4*)aC;
    const float4* n4 = (const float4*)aN;

    // ---- front-batched h load into registers (read-once: streaming) ----
    float4 h[VPT];
#pragma unroll
    for (int i = 0; i < VPT; i++) h[i] = __ldcs(hrow + tid + i * NTHREADS);

    // ---- dot phase: anchors from L1 (48KB resident) ----
    float shh = 0.f, s0 = 0.f, s1 = 0.f, s2 = 0.f;
#pragma unroll
    for (int i = 0; i < VPT; i++) {
        int idx = tid + i * NTHREADS;
        float4 e = __ldg(e4 + idx);
        float4 c = __ldg(c4 + idx);
        float4 n = __ldg(n4 + idx);
        shh += dot4(h[i], h[i]);
        s0  += dot4(h[i], e);
        s1  += dot4(h[i], c);
        s2  += dot4(h[i], n);
    }

    // ---- warp reduce + one 4-warp sync ----
#pragma unroll
    for (int off = 16; off; off >>= 1) {
        shh += __shfl_xor_sync(0xffffffffu, shh, off);
        s0  += __shfl_xor_sync(0xffffffffu, s0, off);
        s1  += __shfl_xor_sync(0xffffffffu, s1, off);
        s2  += __shfl_xor_sync(0xffffffffu, s2, off);
    }
    if (lane == 0) { red[0][warp] = shh; red[1][warp] = s0; red[2][warp] = s1; red[3][warp] = s2; }
    __syncthreads();

    const float hhT = red[0][0] + red[0][1] + red[0][2] + red[0][3];
    const float t0  = red[1][0] + red[1][1] + red[1][2] + red[1][3];
    const float t1  = red[2][0] + red[2][1] + red[2][2] + red[2][3];
    const float t2  = red[3][0] + red[3][1] + red[3][2] + red[3][3];

    const float invn0 = g_stats[0], invn1 = g_stats[1], invn2 = g_stats[2];
    const float G00 = g_stats[3], G11 = g_stats[4], G22 = g_stats[5];
    const float G01 = g_stats[6], G02 = g_stats[7], G12 = g_stats[8];

    // ---- scalar 6-layer recurrence (redundant, uniform across threads) ----
    float hh = hhT;
    float a0 = t0 * invn0, a1 = t1 * invn1, a2 = t2 * invn2;
    float ch = 1.f, c0 = 0.f, c1 = 0.f, c2 = 0.f;

#pragma unroll
    for (int l = 0; l < NUM_LAYERS; l++) {
        float invh = rsqrtf(fmaxf(hh, 1e-24f));
        float al0 = a0 * invh, al1 = a1 * invh, al2 = a2 * invh;
        float dv0 = 1.f - al0, dv1 = 1.f - al1, dv2 = 1.f - al2;
        if (warp == 0 && lane == 0) {
            size_t o = ((size_t)l * BATCH + b) * 3;
            outA[o] = al0; outA[o + 1] = al1; outA[o + 2] = al2;
            outD[o] = dv0; outD[o + 1] = dv1; outD[o + 2] = dv2;
            outT[o] = fmaxf(dv0, 0.f); outT[o + 1] = fmaxf(dv1, 0.f); outT[o + 2] = fmaxf(dv2, 0.f);
        }
        // coef_k = s_k * div_k / ||h - dir_k||  (args O(1e3), rsqrt safe)
        float k0 = 0.10f * dv0 * rsqrtf(fmaxf(hh - 2.f * a0 + G00, 1e-24f));
        float k1 = 0.10f * dv1 * rsqrtf(fmaxf(hh - 2.f * a1 + G11, 1e-24f));
        float k2 = 0.05f * dv2 * rsqrtf(fmaxf(hh - 2.f * a2 + G22, 1e-24f));
        float alpha = 1.f - (k0 + k1 + k2);

        float na0 = alpha * a0 + k0 * G00 + k1 * G01 + k2 * G02;
        float na1 = alpha * a1 + k0 * G01 + k1 * G11 + k2 * G12;
        float na2 = alpha * a2 + k0 * G02 + k1 * G12 + k2 * G22;
        float cross = k0 * k0 * G00 + k1 * k1 * G11 + k2 * k2 * G22
                    + 2.f * (k0 * k1 * G01 + k0 * k2 * G02 + k1 * k2 * G12);
        float nhh = alpha * alpha * hh
                  + 2.f * alpha * (k0 * a0 + k1 * a1 + k2 * a2) + cross;

        ch *= alpha;
        c0 = alpha * c0 + k0;
        c1 = alpha * c1 + k1;
        c2 = alpha * c2 + k2;
        hh = fmaxf(nhh, 0.f);
        a0 = na0; a1 = na1; a2 = na2;

        // norm clamp (uniform branch)
        float nn = sqrtf(hh);
        if (nn > 10.0f) {
            float sc = __fdividef(10.0f, nn + 1e-8f);
            ch *= sc; c0 *= sc; c1 *= sc; c2 *= sc;
            a0 *= sc; a1 *= sc; a2 *= sc;
            hh *= sc * sc;
        }
    }

    const float bE = c0 * invn0, bC = c1 * invn1, bN = c2 * invn2;

    // ---- epilogue: h in registers, anchors from L1, streaming stores ----
    float4* orow = (float4*)(outH + (size_t)b * DIM);
#pragma unroll
    for (int i = 0; i < VPT; i++) {
        int idx = tid + i * NTHREADS;
        float4 e = __ldg(e4 + idx);
        float4 c = __ldg(c4 + idx);
        float4 n = __ldg(n4 + idx);
        float4 o;
        o.x = ch * h[i].x + bE * e.x + bC * c.x + bN * n.x;
        o.y = ch * h[i].y + bE * e.y + bC * c.y + bN * n.y;
        o.z = ch * h[i].z + bE * e.z + bC * c.z + bN * n.z;
        o.w = ch * h[i].w + bE * e.w + bC * c.w + bN * n.w;
        __stcs(orow + idx, o);
    }
}

extern "C" void kernel_launch(void* const* d_in, const int* in_sizes, int n_in,
                              void* d_out, int out_size) {
    const float* h0 = (const float*)d_in[0];
    const float* aE = (const float*)d_in[1];
    const float* aC = (const float*)d_in[2];
    const float* aN = (const float*)d_in[3];
    float* out = (float*)d_out;

    anchor_stats_kernel<<<1, STATS_THREADS>>>(aE, aC, aN);
    collapse_kernel<<<BATCH, NTHREADS>>>(h0, aE, aC, aN, out);
}